// round 3
// baseline (speedup 1.0000x reference)
#include <cuda_runtime.h>
#include <cuda_bf16.h>
#include <math.h>

// Problem dims
#define SEQ    512
#define BATCH  128
#define INDIM  256
#define HID    512
#define ODIM   128

#define CLUSTER 8                     // slice CTAs per batch group
#define NGROUPS 16                    // batch groups
#define BG      8                     // rows per group
#define NC      64                    // cols per slice CTA
#define BH      (BATCH * HID)

// Scratch: xh written by K1, overwritten in-place by h_s during recurrence,
// then consumed by K3. [SEQ][BATCH][HID] fp32 = 134 MB static device array.
__device__ float g_buf[(size_t)SEQ * BATCH * HID];

typedef unsigned long long ull;

__device__ __forceinline__ ull fma2(ull a, ull b, ull c) {
    ull d;
    asm("fma.rn.f32x2 %0, %1, %2, %3;" : "=l"(d) : "l"(a), "l"(b), "l"(c));
    return d;
}
__device__ __forceinline__ void upk(ull v, float& x, float& y) {
    asm("mov.b64 {%0,%1}, %2;" : "=f"(x), "=f"(y) : "l"(v));
}

// ---------------------------------------------------------------------------
// Tiled fp32 GEMM with bias: C[M,N] = A[M,K] @ B[K,N] + bias[N]
// ---------------------------------------------------------------------------
template <int BM, int BN, int BK, int TM, int TN>
__global__ void __launch_bounds__(256, 2)
sgemm_bias_kernel(const float* __restrict__ A,
                  const float* __restrict__ B,
                  const float* __restrict__ bias,
                  float* __restrict__ C,
                  int M, int N, int K) {
    __shared__ float sA[BK][BM + 4];
    __shared__ float sB[BK][BN];

    const int tid = threadIdx.x;
    const int tx = tid % (BN / TN);
    const int ty = tid / (BN / TN);
    const int m0 = blockIdx.y * BM;
    const int n0 = blockIdx.x * BN;

    float acc[TM][TN];
#pragma unroll
    for (int i = 0; i < TM; i++)
#pragma unroll
        for (int j = 0; j < TN; j++) acc[i][j] = 0.0f;

    for (int k0 = 0; k0 < K; k0 += BK) {
#pragma unroll
        for (int i = 0; i < (BM * BK) / (256 * 4); ++i) {
            int idx = tid + i * 256;
            int r   = idx / (BK / 4);
            int kq  = (idx % (BK / 4)) * 4;
            float4 v = *(const float4*)&A[(size_t)(m0 + r) * K + k0 + kq];
            sA[kq + 0][r] = v.x;
            sA[kq + 1][r] = v.y;
            sA[kq + 2][r] = v.z;
            sA[kq + 3][r] = v.w;
        }
#pragma unroll
        for (int i = 0; i < (BK * BN) / (256 * 4); ++i) {
            int idx = tid + i * 256;
            int r   = idx / (BN / 4);
            int cq  = (idx % (BN / 4)) * 4;
            *(float4*)&sB[r][cq] =
                *(const float4*)&B[(size_t)(k0 + r) * N + n0 + cq];
        }
        __syncthreads();

#pragma unroll
        for (int kk = 0; kk < BK; ++kk) {
            float ra[TM], rb[TN];
#pragma unroll
            for (int i = 0; i < TM; i++) ra[i] = sA[kk][ty * TM + i];
#pragma unroll
            for (int j = 0; j < TN; j++) rb[j] = sB[kk][tx * TN + j];
#pragma unroll
            for (int i = 0; i < TM; i++)
#pragma unroll
                for (int j = 0; j < TN; j++) acc[i][j] += ra[i] * rb[j];
        }
        __syncthreads();
    }

#pragma unroll
    for (int i = 0; i < TM; i++) {
        int row = m0 + ty * TM + i;
#pragma unroll
        for (int j = 0; j < TN; j++) {
            int col = n0 + tx * TN + j;
            C[(size_t)row * N + col] = acc[i][j] + bias[col];
        }
    }
}

// ---------------------------------------------------------------------------
// Persistent recurrence kernel, cluster version.
// Grid: 128 CTAs = 16 clusters(batch groups) x 8 ranks(hidden slices).
// CTA (g, c): rows [g*8, g*8+8), cols [c*64, c*64+64).
//
// SMEM: sW4 [256 k-pairs][32 lanes] float4 = (w[k][c0],w[k][c1],
//            w[k+1][c0],w[k+1][c1]) for lane cols c0=cb+2j, c1=cb+2j+1.
//            128 KB, every inner-loop LDS.128 conflict-free.
//       sHd  h_prev duplicated pairs [8 rows][512 k][2] fp32 = 32 KB, so the
//            inner loop needs zero pack instructions: hd.x = (h[k],h[k]).
// Step: compute -> STG h to g_buf[s] -> barrier.cluster (release/acquire,
// flushes L1) -> stage h(s) from L2 via __ldcg into sHd -> __syncthreads.
// No atomics, no fences, no polling.
// ---------------------------------------------------------------------------
#define REC_SMEM_BYTES ((HID * NC + BG * HID * 2) * 4)   // 128KB + 32KB

__global__ void __launch_bounds__(256, 1) __cluster_dims__(CLUSTER, 1, 1)
rnn_recur_kernel(const float* __restrict__ Whh) {
    extern __shared__ float sm[];
    float* sW  = sm;                   // [256][32] float4
    float* sHd = sm + HID * NC;        // [8][512][2] floats

    const int tid = threadIdx.x;
    const int g = blockIdx.x >> 3;
    const int c = blockIdx.x & 7;
    const int cb = c * NC;
    const int rowBase = g * BG;

    // Fill sW4 (one-time). idx = k2*32 + j.
    for (int idx = tid; idx < 256 * 32; idx += 256) {
        int k2 = idx >> 5;
        int j  = idx & 31;
        float2 a = *(const float2*)&Whh[(size_t)(2 * k2) * HID + cb + 2 * j];
        float2 b = *(const float2*)&Whh[(size_t)(2 * k2 + 1) * HID + cb + 2 * j];
        float4 v = make_float4(a.x, a.y, b.x, b.y);
        *(float4*)&sW[idx * 4] = v;
    }
    // h_0 = 0
    for (int idx = tid; idx < BG * HID * 2; idx += 256) sHd[idx] = 0.0f;
    __syncthreads();

    const int b = tid >> 5;            // warp id == batch row within group
    const int j = tid & 31;            // lane: cols cb+2j, cb+2j+1
    const size_t rowOff = (size_t)(rowBase + b) * HID + cb;

    const ulonglong2* wp = (const ulonglong2*)sW + j;       // + k2*32
    const ulonglong2* hp = (const ulonglong2*)(sHd + b * HID * 2);  // [k2]

    // Preload xh[0] for this thread's two columns.
    float2 xh = __ldcg((const float2*)&g_buf[rowOff + 2 * j]);

    for (int s = 0; s < SEQ; ++s) {
        // Prefetch xh for the NEXT step (hides DRAM behind compute).
        float2 pf = make_float2(0.0f, 0.0f);
        if (s + 1 < SEQ)
            pf = __ldcg((const float2*)&g_buf[(size_t)(s + 1) * BH + rowOff + 2 * j]);

        float va = xh.x, vb = xh.y;
        if (s > 0) {
            ull a0 = 0, a1 = 0, a2 = 0, a3 = 0;
#pragma unroll 8
            for (int i = 0; i < 256; i += 2) {
                ulonglong2 w0 = wp[(size_t)i * 32];
                ulonglong2 h0 = hp[i];
                ulonglong2 w1 = wp[(size_t)(i + 1) * 32];
                ulonglong2 h1 = hp[i + 1];
                a0 = fma2(h0.x, w0.x, a0);
                a1 = fma2(h0.y, w0.y, a1);
                a2 = fma2(h1.x, w1.x, a2);
                a3 = fma2(h1.y, w1.y, a3);
            }
            float x0, y0, x1, y1, x2, y2, x3, y3;
            upk(a0, x0, y0); upk(a1, x1, y1);
            upk(a2, x2, y2); upk(a3, x3, y3);
            va += (x0 + x1) + (x2 + x3);
            vb += (y0 + y1) + (y2 + y3);
        }

        float2 hv = make_float2(tanhf(va), tanhf(vb));
        *(float2*)&g_buf[(size_t)s * BH + rowOff + 2 * j] = hv;

        if (s + 1 < SEQ) {
            // Cluster barrier: releases our STG, acquires peers' STGs.
            asm volatile("barrier.cluster.arrive.aligned;" ::: "memory");
            asm volatile("barrier.cluster.wait.aligned;" ::: "memory");

            // Stage h(s)[group rows][all 512 cols] -> sHd (duplicated pairs).
            const float4* src = (const float4*)
                (g_buf + (size_t)s * BH + (size_t)rowBase * HID);
#pragma unroll
            for (int i = 0; i < 4; ++i) {
                int idx = tid + i * 256;           // float4 index (1024 total)
                float4 v = __ldcg(src + idx);
                int r   = idx >> 7;                // 128 float4 per row
                int col = (idx & 127) * 4;
                float* dst = &sHd[(r * HID + col) * 2];
                *(float4*)dst       = make_float4(v.x, v.x, v.y, v.y);
                *(float4*)(dst + 4) = make_float4(v.z, v.z, v.w, v.w);
            }
            __syncthreads();
        }

        xh = pf;
    }
}

// ---------------------------------------------------------------------------
// kernel_launch
// Inputs: x[512,128,256], W_xh[256,512], W_hh[512,512],
//         W_hy[512,128], b_h[512], b_y[128]  -> out[512,128,128] fp32
// ---------------------------------------------------------------------------
extern "C" void kernel_launch(void* const* d_in, const int* in_sizes, int n_in,
                              void* d_out, int out_size) {
    const float* x   = (const float*)d_in[0];
    const float* Wxh = (const float*)d_in[1];
    const float* Whh = (const float*)d_in[2];
    const float* Why = (const float*)d_in[3];
    const float* bh  = (const float*)d_in[4];
    const float* by  = (const float*)d_in[5];
    float* out = (float*)d_out;

    float* buf = nullptr;
    cudaGetSymbolAddress((void**)&buf, g_buf);

    cudaFuncSetAttribute(rnn_recur_kernel,
                         cudaFuncAttributeMaxDynamicSharedMemorySize,
                         REC_SMEM_BYTES);

    // 1) xh = x @ W_xh + b_h   -> g_buf
    {
        dim3 grid(HID / 64, (SEQ * BATCH) / 128);
        sgemm_bias_kernel<128, 64, 16, 8, 4><<<grid, 256>>>(
            x, Wxh, bh, buf, SEQ * BATCH, HID, INDIM);
    }

    // 2) recurrence: h_s = tanh(xh_s + h_{s-1} @ W_hh), in-place in g_buf
    //    16 clusters of 8 CTAs.
    rnn_recur_kernel<<<NGROUPS * CLUSTER, 256, REC_SMEM_BYTES>>>(Whh);

    // 3) out = hs @ W_hy + b_y
    {
        dim3 grid(ODIM / 64, (SEQ * BATCH) / 128);
        sgemm_bias_kernel<128, 64, 16, 8, 4><<<grid, 256>>>(
            buf, Why, by, out, SEQ * BATCH, ODIM, HID);
    }
}

// round 4
// speedup vs baseline: 2.2254x; 2.2254x over previous
#include <cuda_runtime.h>
#include <cuda_bf16.h>
#include <math.h>

// Problem dims
#define SEQ    512
#define BATCH  128
#define INDIM  256
#define HID    512
#define ODIM   128
#define BH     (BATCH * HID)

// Recurrence decomposition: 8 batch groups x 16 hidden slices = 128 CTAs.
#define NG     8                    // batch groups
#define NS     16                   // hidden slices
#define BGR    16                   // rows per group
#define NCR    32                   // cols per slice
#define KCH    32                   // k per warp (16 warps x 32 = 512)
#define HTS    20                   // sHt row stride in floats (16B-aligned pad)

// Scratch: xh written by K1, overwritten in-place by h_s, consumed by K3.
__device__ float g_buf[(size_t)SEQ * BATCH * HID];
// Per-(step,group) completion counters (16 slice producers each).
__device__ int g_flags[SEQ * NG];

typedef unsigned long long ull;

__device__ __forceinline__ ull fma2(ull a, ull b, ull c) {
    ull d;
    asm("fma.rn.f32x2 %0, %1, %2, %3;" : "=l"(d) : "l"(a), "l"(b), "l"(c));
    return d;
}
__device__ __forceinline__ void upk(ull v, float& x, float& y) {
    asm("mov.b64 {%0,%1}, %2;" : "=f"(x), "=f"(y) : "l"(v));
}
__device__ __forceinline__ ull dup2(float v) {
    ull d;
    asm("mov.b64 %0, {%1,%1};" : "=l"(d) : "f"(v));
    return d;
}
__device__ __forceinline__ int ldacq(const int* p) {
    int v;
    asm volatile("ld.acquire.gpu.b32 %0, [%1];" : "=r"(v) : "l"(p));
    return v;
}

// ---------------------------------------------------------------------------
__global__ void zero_flags_kernel() {
    int i = blockIdx.x * blockDim.x + threadIdx.x;
    if (i < SEQ * NG) g_flags[i] = 0;
}

// ---------------------------------------------------------------------------
// Tiled fp32 GEMM with bias: C[M,N] = A[M,K] @ B[K,N] + bias[N]
// ---------------------------------------------------------------------------
template <int BM, int BN, int BK, int TM, int TN>
__global__ void __launch_bounds__(256, 2)
sgemm_bias_kernel(const float* __restrict__ A,
                  const float* __restrict__ B,
                  const float* __restrict__ bias,
                  float* __restrict__ C,
                  int M, int N, int K) {
    __shared__ float sA[BK][BM + 4];
    __shared__ float sB[BK][BN];

    const int tid = threadIdx.x;
    const int tx = tid % (BN / TN);
    const int ty = tid / (BN / TN);
    const int m0 = blockIdx.y * BM;
    const int n0 = blockIdx.x * BN;

    float acc[TM][TN];
#pragma unroll
    for (int i = 0; i < TM; i++)
#pragma unroll
        for (int j = 0; j < TN; j++) acc[i][j] = 0.0f;

    for (int k0 = 0; k0 < K; k0 += BK) {
#pragma unroll
        for (int i = 0; i < (BM * BK) / (256 * 4); ++i) {
            int idx = tid + i * 256;
            int r   = idx / (BK / 4);
            int kq  = (idx % (BK / 4)) * 4;
            float4 v = *(const float4*)&A[(size_t)(m0 + r) * K + k0 + kq];
            sA[kq + 0][r] = v.x;
            sA[kq + 1][r] = v.y;
            sA[kq + 2][r] = v.z;
            sA[kq + 3][r] = v.w;
        }
#pragma unroll
        for (int i = 0; i < (BK * BN) / (256 * 4); ++i) {
            int idx = tid + i * 256;
            int r   = idx / (BN / 4);
            int cq  = (idx % (BN / 4)) * 4;
            *(float4*)&sB[r][cq] =
                *(const float4*)&B[(size_t)(k0 + r) * N + n0 + cq];
        }
        __syncthreads();

#pragma unroll
        for (int kk = 0; kk < BK; ++kk) {
            float ra[TM], rb[TN];
#pragma unroll
            for (int i = 0; i < TM; i++) ra[i] = sA[kk][ty * TM + i];
#pragma unroll
            for (int j = 0; j < TN; j++) rb[j] = sB[kk][tx * TN + j];
#pragma unroll
            for (int i = 0; i < TM; i++)
#pragma unroll
                for (int j = 0; j < TN; j++) acc[i][j] += ra[i] * rb[j];
        }
        __syncthreads();
    }

#pragma unroll
    for (int i = 0; i < TM; i++) {
        int row = m0 + ty * TM + i;
#pragma unroll
        for (int j = 0; j < TN; j++) {
            int col = n0 + tx * TN + j;
            C[(size_t)row * N + col] = acc[i][j] + bias[col];
        }
    }
}

// ---------------------------------------------------------------------------
// Persistent recurrence kernel: W-in-registers, k-split across warps.
// Grid: 128 CTAs = 8 groups x 16 slices, 512 threads (16 warps).
// CTA (g,c): rows [g*16, g*16+16), cols [c*32, c*32+32).
// Warp w: k-chunk [w*32, w*32+32). Lane j: column cb+j.
//   - W[k][cb+j] for the thread's 32 k preloaded in registers (step-invariant)
//     => ZERO per-step SMEM traffic for W (was 1 MB/step/CTA in R2).
//   - h staged transposed: sHt[k][16 rows] (pad 20); inner loop per k:
//     4x LDS.128 broadcast (16 rows as 8 row-pairs) + 1 dup-mov + 8 FFMA2.
//   - Partials across 16 warps reduced via SMEM transpose sRd[r][ww][c]
//     (both write and read conflict-free), then thread (r,c)=(w,j) adds xh,
//     applies tanh, stores h.
// Exchange: R2-proven global flag counter (release-fence + red; acquire poll).
// ---------------------------------------------------------------------------
#define REC_SMEM_BYTES ((HID * HTS + BGR * NS * NCR) * 4)   // 40KB + 32KB

__global__ void __launch_bounds__(512, 1)
rnn_recur_kernel(const float* __restrict__ Whh) {
    extern __shared__ float sm[];
    float* sHt = sm;                     // [512][HTS]
    float* sRd = sm + HID * HTS;         // [16 r][16 ww][32 c]

    const int tid = threadIdx.x;
    const int w = tid >> 5;              // warp = k-chunk AND output row
    const int j = tid & 31;              // lane = column
    const int g = blockIdx.x >> 4;       // batch group 0..7
    const int c = blockIdx.x & 15;       // slice 0..15
    const int cb = c * NCR;
    const int rowBase = g * BGR;

    // Preload W column slice into registers (coalesced, one-time).
    float wreg[KCH];
#pragma unroll
    for (int kk = 0; kk < KCH; ++kk)
        wreg[kk] = Whh[(size_t)(w * KCH + kk) * HID + cb + j];

    // Output mapping: (row, col) = (w, j).
    const size_t rowOffR = (size_t)(rowBase + w) * HID + cb + j;

    float xh = __ldcg(&g_buf[rowOffR]);          // xh[0]

    for (int s = 0; s < SEQ; ++s) {
        // Prefetch next xh before the wait (hides DRAM under the poll).
        float pf = 0.0f;
        if (s + 1 < SEQ)
            pf = __ldcg(&g_buf[(size_t)(s + 1) * BH + rowOffR]);

        float val = xh;
        if (s > 0) {
            if (tid == 0) {
                while (ldacq(&g_flags[(s - 1) * NG + g]) < NS) { }
            }
            __syncthreads();

            // Stage h[s-1][group rows][all 512 cols] -> sHt (transposed).
            const float4* src = (const float4*)
                (g_buf + (size_t)(s - 1) * BH + (size_t)rowBase * HID);
#pragma unroll
            for (int i = 0; i < 4; ++i) {
                int idx = tid + i * 512;          // 2048 float4 = 16x512
                float4 v = __ldcg(src + idx);
                int r  = idx >> 7;                // row
                int k4 = (idx & 127) << 2;        // k base
                sHt[(k4 + 0) * HTS + r] = v.x;
                sHt[(k4 + 1) * HTS + r] = v.y;
                sHt[(k4 + 2) * HTS + r] = v.z;
                sHt[(k4 + 3) * HTS + r] = v.w;
            }
            __syncthreads();

            // Partial dot over this warp's k-chunk for 16 rows x 1 col.
            ull acc[8];
#pragma unroll
            for (int p = 0; p < 8; ++p) acc[p] = 0;

            const float* hb = sHt + (size_t)(w * KCH) * HTS;
#pragma unroll
            for (int kk = 0; kk < KCH; ++kk) {
                const ulonglong2* hp = (const ulonglong2*)(hb + kk * HTS);
                ulonglong2 hA = hp[0];            // rows 0..3
                ulonglong2 hB = hp[1];            // rows 4..7
                ulonglong2 hC = hp[2];            // rows 8..11
                ulonglong2 hD = hp[3];            // rows 12..15
                ull wd = dup2(wreg[kk]);
                acc[0] = fma2(hA.x, wd, acc[0]);
                acc[1] = fma2(hA.y, wd, acc[1]);
                acc[2] = fma2(hB.x, wd, acc[2]);
                acc[3] = fma2(hB.y, wd, acc[3]);
                acc[4] = fma2(hC.x, wd, acc[4]);
                acc[5] = fma2(hC.y, wd, acc[5]);
                acc[6] = fma2(hD.x, wd, acc[6]);
                acc[7] = fma2(hD.y, wd, acc[7]);
            }

            // Write partials transposed: sRd[r][w][j] (conflict-free STS.32).
#pragma unroll
            for (int p = 0; p < 8; ++p) {
                float lo, hi;
                upk(acc[p], lo, hi);
                sRd[((2 * p)     * NS + w) * NCR + j] = lo;
                sRd[((2 * p + 1) * NS + w) * NCR + j] = hi;
            }
            __syncthreads();

            // Reduce 16 partials for (r=w, c=j) — conflict-free LDS.32.
            float sum = 0.0f;
#pragma unroll
            for (int ww = 0; ww < NS; ++ww)
                sum += sRd[(w * NS + ww) * NCR + j];
            val += sum;
        }

        float h = tanhf(val);
        g_buf[(size_t)s * BH + rowOffR] = h;      // coalesced per warp

        __syncthreads();
        if (tid == 0) {
            __threadfence();
            atomicAdd(&g_flags[s * NG + g], 1);
        }

        xh = pf;
    }
}

// ---------------------------------------------------------------------------
// kernel_launch
// Inputs: x[512,128,256], W_xh[256,512], W_hh[512,512],
//         W_hy[512,128], b_h[512], b_y[128]  -> out[512,128,128] fp32
// ---------------------------------------------------------------------------
extern "C" void kernel_launch(void* const* d_in, const int* in_sizes, int n_in,
                              void* d_out, int out_size) {
    const float* x   = (const float*)d_in[0];
    const float* Wxh = (const float*)d_in[1];
    const float* Whh = (const float*)d_in[2];
    const float* Why = (const float*)d_in[3];
    const float* bh  = (const float*)d_in[4];
    const float* by  = (const float*)d_in[5];
    float* out = (float*)d_out;

    float* buf = nullptr;
    cudaGetSymbolAddress((void**)&buf, g_buf);

    cudaFuncSetAttribute(rnn_recur_kernel,
                         cudaFuncAttributeMaxDynamicSharedMemorySize,
                         REC_SMEM_BYTES);

    // 0) zero the per-step flags (deterministic per graph replay)
    zero_flags_kernel<<<(SEQ * NG + 255) / 256, 256>>>();

    // 1) xh = x @ W_xh + b_h -> g_buf
    {
        dim3 grid(HID / 64, (SEQ * BATCH) / 128);
        sgemm_bias_kernel<128, 64, 16, 8, 4><<<grid, 256>>>(
            x, Wxh, bh, buf, SEQ * BATCH, HID, INDIM);
    }

    // 2) recurrence: h_s = tanh(xh_s + h_{s-1} @ W_hh), in-place in g_buf
    rnn_recur_kernel<<<NG * NS, 512, REC_SMEM_BYTES>>>(Whh);

    // 3) out = hs @ W_hy + b_y
    {
        dim3 grid(ODIM / 64, (SEQ * BATCH) / 128);
        sgemm_bias_kernel<128, 64, 16, 8, 4><<<grid, 256>>>(
            buf, Why, by, out, SEQ * BATCH, ODIM, HID);
    }
}

// round 5
// speedup vs baseline: 3.1714x; 1.4251x over previous
#include <cuda_runtime.h>
#include <cuda_bf16.h>
#include <math.h>

// Problem dims
#define SEQ    512
#define BATCH  128
#define INDIM  256
#define HID    512
#define ODIM   128
#define BH     (BATCH * HID)

// Recurrence decomposition: 8 batch groups x 16 hidden slices = 128 CTAs.
#define NG     8                    // batch groups
#define NS     16                   // hidden slices (producers per group flag)
#define BGR    16                   // rows per group (= warps per CTA)
#define NCR    32                   // cols per slice (= lanes)
#define KCH    32                   // k per warp (16 warps x 32 = 512)
#define FST    544                  // per-group flag stride (ints)

// Scratch: xh written by K1, overwritten in-place by h_s, consumed by K3.
__device__ float g_buf[(size_t)SEQ * BATCH * HID];
// Per-(group,step) completion counters, padded per group.
__device__ int g_flags[NG * FST];

typedef unsigned long long ull;

__device__ __forceinline__ ull fma2(ull a, ull b, ull c) {
    ull d;
    asm("fma.rn.f32x2 %0, %1, %2, %3;" : "=l"(d) : "l"(a), "l"(b), "l"(c));
    return d;
}
__device__ __forceinline__ void upk(ull v, float& x, float& y) {
    asm("mov.b64 {%0,%1}, %2;" : "=f"(x), "=f"(y) : "l"(v));
}
__device__ __forceinline__ ull pk(float x, float y) {
    ull d;
    asm("mov.b64 %0, {%1,%2};" : "=l"(d) : "f"(x), "f"(y));
    return d;
}
__device__ __forceinline__ int ldacq(const int* p) {
    int v;
    asm volatile("ld.acquire.gpu.b32 %0, [%1];" : "=r"(v) : "l"(p));
    return v;
}
__device__ __forceinline__ void red_release(int* p, int v) {
    asm volatile("red.release.gpu.global.add.s32 [%0], %1;" :: "l"(p), "r"(v)
                 : "memory");
}

// ---------------------------------------------------------------------------
__global__ void zero_flags_kernel() {
    int i = blockIdx.x * blockDim.x + threadIdx.x;
    if (i < NG * FST) g_flags[i] = 0;
}

// ---------------------------------------------------------------------------
// Tiled fp32 GEMM with bias: C[M,N] = A[M,K] @ B[K,N] + bias[N]
// ---------------------------------------------------------------------------
template <int BM, int BN, int BK, int TM, int TN>
__global__ void __launch_bounds__(256, 2)
sgemm_bias_kernel(const float* __restrict__ A,
                  const float* __restrict__ B,
                  const float* __restrict__ bias,
                  float* __restrict__ C,
                  int M, int N, int K) {
    __shared__ float sA[BK][BM + 4];
    __shared__ float sB[BK][BN];

    const int tid = threadIdx.x;
    const int tx = tid % (BN / TN);
    const int ty = tid / (BN / TN);
    const int m0 = blockIdx.y * BM;
    const int n0 = blockIdx.x * BN;

    float acc[TM][TN];
#pragma unroll
    for (int i = 0; i < TM; i++)
#pragma unroll
        for (int j = 0; j < TN; j++) acc[i][j] = 0.0f;

    for (int k0 = 0; k0 < K; k0 += BK) {
#pragma unroll
        for (int i = 0; i < (BM * BK) / (256 * 4); ++i) {
            int idx = tid + i * 256;
            int r   = idx / (BK / 4);
            int kq  = (idx % (BK / 4)) * 4;
            float4 v = *(const float4*)&A[(size_t)(m0 + r) * K + k0 + kq];
            sA[kq + 0][r] = v.x;
            sA[kq + 1][r] = v.y;
            sA[kq + 2][r] = v.z;
            sA[kq + 3][r] = v.w;
        }
#pragma unroll
        for (int i = 0; i < (BK * BN) / (256 * 4); ++i) {
            int idx = tid + i * 256;
            int r   = idx / (BN / 4);
            int cq  = (idx % (BN / 4)) * 4;
            *(float4*)&sB[r][cq] =
                *(const float4*)&B[(size_t)(k0 + r) * N + n0 + cq];
        }
        __syncthreads();

#pragma unroll
        for (int kk = 0; kk < BK; ++kk) {
            float ra[TM], rb[TN];
#pragma unroll
            for (int i = 0; i < TM; i++) ra[i] = sA[kk][ty * TM + i];
#pragma unroll
            for (int j = 0; j < TN; j++) rb[j] = sB[kk][tx * TN + j];
#pragma unroll
            for (int i = 0; i < TM; i++)
#pragma unroll
                for (int j = 0; j < TN; j++) acc[i][j] += ra[i] * rb[j];
        }
        __syncthreads();
    }

#pragma unroll
    for (int i = 0; i < TM; i++) {
        int row = m0 + ty * TM + i;
#pragma unroll
        for (int j = 0; j < TN; j++) {
            int col = n0 + tx * TN + j;
            C[(size_t)row * N + col] = acc[i][j] + bias[col];
        }
    }
}

// ---------------------------------------------------------------------------
// Persistent recurrence kernel.
// Grid: 128 CTAs = 8 groups x 16 slices, 512 threads (16 warps).
// CTA (g,c): rows [g*16,+16), cols [c*32,+32). Warp w: k-chunk [w*32,+32).
// Lane j: column cb+j. W k-pairs pre-packed in registers (step-invariant).
//
// Per step (serial chain):
//   all-thread ld.acquire poll -> stage h[s-1] rows into sHt[r][512]
//   (LDG.128 coalesced, STS.128 conflict-free) -> bar -> per-(row,4k):
//   1 broadcast LDS.128 + 2 FFMA2 (even/odd-k packed accs, zero pack movs)
//   -> cross-warp reduce via sRd (conflict-free) -> tanh -> STG -> bar ->
//   tid0 red.release.gpu on group flag.
// ---------------------------------------------------------------------------
#define REC_SMEM_BYTES ((BGR * HID + BGR * NS * NCR) * 4)   // 32KB + 32KB

__global__ void __launch_bounds__(512, 1)
rnn_recur_kernel(const float* __restrict__ Whh) {
    extern __shared__ float sm[];
    float* sHt = sm;                     // [16 r][512 k]
    float* sRd = sm + BGR * HID;         // [16 r][16 ww][32 c]

    const int tid = threadIdx.x;
    const int w = tid >> 5;              // warp = k-chunk AND output row
    const int j = tid & 31;              // lane = column
    const int g = blockIdx.x >> 4;       // batch group 0..7
    const int c = blockIdx.x & 15;       // slice 0..15
    const int cb = c * NCR;
    const int rowBase = g * BGR;
    const int K0 = w * KCH;

    // Preload W k-pairs into registers: wp[p] = (W[K0+2p][cb+j], W[K0+2p+1][cb+j])
    ull wp[KCH / 2];
#pragma unroll
    for (int p = 0; p < KCH / 2; ++p) {
        float lo = Whh[(size_t)(K0 + 2 * p)     * HID + cb + j];
        float hi = Whh[(size_t)(K0 + 2 * p + 1) * HID + cb + j];
        wp[p] = pk(lo, hi);
    }

    // Output mapping: (row, col) = (w, j).
    const size_t rowOffR = (size_t)(rowBase + w) * HID + cb + j;
    int* const flags = g_flags + g * FST;

    float xh = __ldcg(&g_buf[rowOffR]);          // xh[0]

    for (int s = 0; s < SEQ; ++s) {
        float pf = 0.0f;
        if (s + 1 < SEQ)
            pf = __ldcg(&g_buf[(size_t)(s + 1) * BH + rowOffR]);

        float val = xh;
        if (s > 0) {
            // All threads poll (warp-uniform L2 read).
            while (ldacq(&flags[s - 1]) < NS) { }

            // Stage h[s-1][16 rows][512 cols] -> sHt[r][k] (no transpose).
            const float4* src = (const float4*)
                (g_buf + (size_t)(s - 1) * BH + (size_t)rowBase * HID);
#pragma unroll
            for (int i = 0; i < 4; ++i) {
                int idx = tid + i * 512;          // 2048 float4 = 16x128
                ((float4*)sHt)[idx] = __ldcg(src + idx);
            }
            __syncthreads();

            // Partial dot over this warp's 32 k for 16 rows x 1 col.
            // acc[r] = (even-k sum, odd-k sum) packed.
            ull acc[BGR];
#pragma unroll
            for (int r = 0; r < BGR; ++r) acc[r] = 0;

#pragma unroll
            for (int t = 0; t < KCH / 4; ++t) {   // 4 k per iteration
                const int k = K0 + 4 * t;
#pragma unroll
                for (int r = 0; r < BGR; ++r) {
                    ulonglong2 h2 = *(const ulonglong2*)&sHt[r * HID + k];
                    acc[r] = fma2(h2.x, wp[2 * t],     acc[r]);
                    acc[r] = fma2(h2.y, wp[2 * t + 1], acc[r]);
                }
            }

            // Partials -> sRd[r][w][j] (lane-consecutive, conflict-free).
#pragma unroll
            for (int r = 0; r < BGR; ++r) {
                float lo, hi;
                upk(acc[r], lo, hi);
                sRd[(r * NS + w) * NCR + j] = lo + hi;
            }
            __syncthreads();

            // Reduce 16 k-chunk partials for (row=w, col=j).
            float sum = 0.0f;
#pragma unroll
            for (int ww = 0; ww < NS; ++ww)
                sum += sRd[(w * NS + ww) * NCR + j];
            val += sum;
        }

        float h = tanhf(val);
        g_buf[(size_t)s * BH + rowOffR] = h;      // coalesced per warp

        __syncthreads();
        if (tid == 0) red_release(&flags[s], 1);

        xh = pf;
    }
}

// ---------------------------------------------------------------------------
// kernel_launch
// Inputs: x[512,128,256], W_xh[256,512], W_hh[512,512],
//         W_hy[512,128], b_h[512], b_y[128]  -> out[512,128,128] fp32
// ---------------------------------------------------------------------------
extern "C" void kernel_launch(void* const* d_in, const int* in_sizes, int n_in,
                              void* d_out, int out_size) {
    const float* x   = (const float*)d_in[0];
    const float* Wxh = (const float*)d_in[1];
    const float* Whh = (const float*)d_in[2];
    const float* Why = (const float*)d_in[3];
    const float* bh  = (const float*)d_in[4];
    const float* by  = (const float*)d_in[5];
    float* out = (float*)d_out;

    float* buf = nullptr;
    cudaGetSymbolAddress((void**)&buf, g_buf);

    cudaFuncSetAttribute(rnn_recur_kernel,
                         cudaFuncAttributeMaxDynamicSharedMemorySize,
                         REC_SMEM_BYTES);

    // 0) zero the per-step flags (deterministic per graph replay)
    zero_flags_kernel<<<(NG * FST + 255) / 256, 256>>>();

    // 1) xh = x @ W_xh + b_h -> g_buf
    {
        dim3 grid(HID / 64, (SEQ * BATCH) / 128);
        sgemm_bias_kernel<128, 64, 16, 8, 4><<<grid, 256>>>(
            x, Wxh, bh, buf, SEQ * BATCH, HID, INDIM);
    }

    // 2) recurrence: h_s = tanh(xh_s + h_{s-1} @ W_hh), in-place in g_buf
    rnn_recur_kernel<<<NG * NS, 512, REC_SMEM_BYTES>>>(Whh);

    // 3) out = hs @ W_hy + b_y
    {
        dim3 grid(ODIM / 64, (SEQ * BATCH) / 128);
        sgemm_bias_kernel<128, 64, 16, 8, 4><<<grid, 256>>>(
            buf, Why, by, out, SEQ * BATCH, ODIM, HID);
    }
}